// round 5
// baseline (speedup 1.0000x reference)
#include <cuda_runtime.h>

#define D 8
#define H 256
#define MAXN 100352
#define MASKW (H/32)
typedef unsigned long long u64;

// ---------------- scratch (device globals; zero-initialized at module load).
// Invariant: all accumulator arrays are zero on entry to kernel_launch and are
// re-zeroed by the kernel that consumes them (graph-replay safe).
__device__ float d_mdiag[MAXN*D];
__device__ float d_qs[MAXN*D];     // q * norm_src
__device__ float d_nsrc[MAXN];
__device__ float d_ndst[MAXN];
__device__ int   d_degout[MAXN];   // accumulator (zeroed by k_prep)
__device__ int   d_degin[MAXN];    // accumulator (zeroed by k_prep)
__device__ float d_agg1[MAXN*D];   // accumulator (zeroed by k_mlp_fwd)
__device__ float d_ts[MAXN*D];
__device__ float d_agg2[MAXN*D];   // accumulator (zeroed by k_h)
__device__ float d_h[MAXN*D];
__device__ float d_gH[MAXN*D];     // accumulator (zeroed by k_final)
__device__ float d_gz1d[MAXN*D];
__device__ float d_tmp1[MAXN*D];   // accumulator (zeroed by k_mlp_bwd)
__device__ float d_tmp2[MAXN*D];   // accumulator (zeroed by k_final)
__device__ unsigned d_mask[MAXN*MASKW];

// ---------------- helpers ---------------------------------------------------
__device__ __forceinline__ void red_add_v4(float* p, float4 v) {
    asm volatile("red.global.add.v4.f32 [%0], {%1,%2,%3,%4};"
                 :: "l"(p), "f"(v.x), "f"(v.y), "f"(v.z), "f"(v.w) : "memory");
}
__device__ __forceinline__ u64 pk(float a, float b) {
    u64 r; asm("mov.b64 %0, {%1,%2};" : "=l"(r) : "f"(a), "f"(b)); return r;
}
__device__ __forceinline__ void upk(u64 v, float& a, float& b) {
    asm("mov.b64 {%0,%1}, %2;" : "=f"(a), "=f"(b) : "l"(v));
}
__device__ __forceinline__ u64 fma2(u64 a, u64 b, u64 c) {
    u64 r; asm("fma.rn.f32x2 %0, %1, %2, %3;" : "=l"(r) : "l"(a), "l"(b), "l"(c)); return r;
}

// ---------------- degree count (4 edges/thread) ------------------------------
__global__ void k_deg(const int* __restrict__ src, const int* __restrict__ dst, int e) {
    int t = blockIdx.x * blockDim.x + threadIdx.x;
    int base = t * 4;
    if (base + 4 <= e) {
        int4 s4 = *(const int4*)(src + base);
        int4 t4 = *(const int4*)(dst + base);
        atomicAdd(&d_degout[s4.x], 1); atomicAdd(&d_degout[s4.y], 1);
        atomicAdd(&d_degout[s4.z], 1); atomicAdd(&d_degout[s4.w], 1);
        atomicAdd(&d_degin[t4.x], 1);  atomicAdd(&d_degin[t4.y], 1);
        atomicAdd(&d_degin[t4.z], 1);  atomicAdd(&d_degin[t4.w], 1);
    } else {
        for (int i = base; i < e; i++) {
            atomicAdd(&d_degout[src[i]], 1);
            atomicAdd(&d_degin[dst[i]], 1);
        }
    }
}

// ---------------- prep: norms, mass diag, qs, dHdP; zero deg counters --------
__global__ void k_prep(const float* __restrict__ q, const float* __restrict__ p,
                       const float* __restrict__ M, float* __restrict__ out, int n) {
    int i = blockIdx.x * blockDim.x + threadIdx.x;
    if (i >= n) return;
    int dout = d_degout[i], din = d_degin[i];
    d_degout[i] = 0; d_degin[i] = 0;                      // restore invariant
    float ns = (dout > 0) ? rsqrtf((float)dout) : 1.0f;
    float nd = (din  > 0) ? rsqrtf((float)din)  : 1.0f;
    d_nsrc[i] = ns; d_ndst[i] = nd;
#pragma unroll
    for (int d0 = 0; d0 < D; d0++) {
        float m = M[(size_t)i * (D*D) + d0 * (D+1)];
        d_mdiag[i*D + d0] = m;
        d_qs[i*D + d0] = q[i*D + d0] * ns;
        out[(size_t)i*16 + 8 + d0] = p[i*D + d0] / m;     // dHdP
    }
}

// ---------------- generic edge aggregation (4 edges/thread) ------------------
__device__ __forceinline__ void edge_agg4(const int* __restrict__ gi, const int* __restrict__ si,
                                          const float* __restrict__ xin, float* xout, int e) {
    int t = blockIdx.x * blockDim.x + threadIdx.x;
    int base = t * 4;
    if (base + 4 <= e) {
        int4 g4 = *(const int4*)(gi + base);
        int4 s4 = *(const int4*)(si + base);
        int g[4] = {g4.x, g4.y, g4.z, g4.w};
        int s[4] = {s4.x, s4.y, s4.z, s4.w};
        float4 a[4], b[4];
#pragma unroll
        for (int k = 0; k < 4; k++) {
            const float4* ps = (const float4*)(xin + (size_t)g[k] * D);
            a[k] = __ldg(ps); b[k] = __ldg(ps + 1);
        }
#pragma unroll
        for (int k = 0; k < 4; k++) {
            float* po = xout + (size_t)s[k] * D;
            red_add_v4(po, a[k]); red_add_v4(po + 4, b[k]);
        }
    } else {
        for (int i = base; i < e; i++) {
            int g = gi[i], s = si[i];
            const float4* ps = (const float4*)(xin + (size_t)g * D);
            float4 a = __ldg(ps), b = __ldg(ps + 1);
            float* po = xout + (size_t)s * D;
            red_add_v4(po, a); red_add_v4(po + 4, b);
        }
    }
}

__global__ void k_agg1(const int* __restrict__ src, const int* __restrict__ dst, int e)
{ edge_agg4(src, dst, d_qs, d_agg1, e); }
__global__ void k_agg2(const int* __restrict__ src, const int* __restrict__ dst, int e)
{ edge_agg4(src, dst, d_ts, d_agg2, e); }
__global__ void k_aggr2(const int* __restrict__ src, const int* __restrict__ dst, int e)
{ edge_agg4(dst, src, d_gz1d, d_tmp2, e); }

// aggr1 folds the ndst scaling into the gather: tmp1[src] += gH[dst] * ndst[dst]
__global__ void k_aggr1(const int* __restrict__ src, const int* __restrict__ dst, int e) {
    int t = blockIdx.x * blockDim.x + threadIdx.x;
    int base = t * 4;
    if (base + 4 <= e) {
        int4 g4 = *(const int4*)(dst + base);
        int4 s4 = *(const int4*)(src + base);
        int g[4] = {g4.x, g4.y, g4.z, g4.w};
        int s[4] = {s4.x, s4.y, s4.z, s4.w};
        float4 a[4], b[4]; float nd[4];
#pragma unroll
        for (int k = 0; k < 4; k++) {
            const float4* ps = (const float4*)(d_gH + (size_t)g[k] * D);
            a[k] = __ldg(ps); b[k] = __ldg(ps + 1);
            nd[k] = __ldg(&d_ndst[g[k]]);
        }
#pragma unroll
        for (int k = 0; k < 4; k++) {
            float4 av = a[k], bv = b[k]; float s0 = nd[k];
            av.x *= s0; av.y *= s0; av.z *= s0; av.w *= s0;
            bv.x *= s0; bv.y *= s0; bv.z *= s0; bv.w *= s0;
            float* po = d_tmp1 + (size_t)s[k] * D;
            red_add_v4(po, av); red_add_v4(po + 4, bv);
        }
    } else {
        for (int i = base; i < e; i++) {
            int g = dst[i], s = src[i];
            float s0 = __ldg(&d_ndst[g]);
            const float4* ps = (const float4*)(d_gH + (size_t)g * D);
            float4 a = __ldg(ps), b = __ldg(ps + 1);
            a.x *= s0; a.y *= s0; a.z *= s0; a.w *= s0;
            b.x *= s0; b.y *= s0; b.z *= s0; b.w *= s0;
            float* po = d_tmp1 + (size_t)s * D;
            red_add_v4(po, a); red_add_v4(po + 4, b);
        }
    }
}

// ---------------- MLP forward (packed f32x2 over j-pairs) --------------------
__global__ __launch_bounds__(256) void k_mlp_fwd(const float* __restrict__ W1,
                                                 const float* __restrict__ b1,
                                                 const float* __restrict__ W2, int n) {
    __shared__ ulonglong2 sW1p[H/2][4];  // [jp][d/2]: ((W1[d][2jp],W1[d][2jp+1]) pairs)
    __shared__ ulonglong2 sW2p[H][2];    // [j]: row W2[j][0..7] packed in d-pairs
    __shared__ u64 sb1p[H/2];
    int tid = threadIdx.x;
    {   // stage weights
        float4 wa = ((const float4*)W2)[tid*2], wb = ((const float4*)W2)[tid*2+1];
        sW2p[tid][0] = make_ulonglong2(pk(wa.x, wa.y), pk(wa.z, wa.w));
        sW2p[tid][1] = make_ulonglong2(pk(wb.x, wb.y), pk(wb.z, wb.w));
        if (tid < H/2) {
            int jp = tid;
            u64* w = (u64*)sW1p[jp];
#pragma unroll
            for (int d0 = 0; d0 < D; d0++)
                w[d0] = pk(W1[d0*H + 2*jp], W1[d0*H + 2*jp + 1]);
            sb1p[jp] = pk(b1[2*jp], b1[2*jp + 1]);
        }
    }
    __syncthreads();
    int i = blockIdx.x * blockDim.x + tid;
    if (i >= n) return;
    float nd = d_ndst[i], ns = d_nsrc[i];
    float4* pz = (float4*)(d_agg1 + (size_t)i * D);
    float4 z0 = pz[0], z1 = pz[1];
    pz[0] = make_float4(0.f,0.f,0.f,0.f);               // restore invariant
    pz[1] = make_float4(0.f,0.f,0.f,0.f);
    float zz[8] = {z0.x*nd, z0.y*nd, z0.z*nd, z0.w*nd, z1.x*nd, z1.y*nd, z1.z*nd, z1.w*nd};
    u64 zp[8];
#pragma unroll
    for (int d0 = 0; d0 < D; d0++) zp[d0] = pk(zz[d0], zz[d0]);
    u64 zero2 = pk(0.f, 0.f);
    u64 tp[4] = {zero2, zero2, zero2, zero2};
    unsigned mword = 0;
#pragma unroll 4
    for (int jp = 0; jp < H/2; jp++) {
        u64 acc = sb1p[jp];
        ulonglong2 wA = sW1p[jp][0], wB = sW1p[jp][1], wC = sW1p[jp][2], wD = sW1p[jp][3];
        acc = fma2(zp[0], wA.x, acc); acc = fma2(zp[1], wA.y, acc);
        acc = fma2(zp[2], wB.x, acc); acc = fma2(zp[3], wB.y, acc);
        acc = fma2(zp[4], wC.x, acc); acc = fma2(zp[5], wC.y, acc);
        acc = fma2(zp[6], wD.x, acc); acc = fma2(zp[7], wD.y, acc);
        float y0, y1; upk(acc, y0, y1);
        int j0 = 2*jp;
        mword |= (y0 > 0.f ? 1u : 0u) << (j0 & 31);
        mword |= (y1 > 0.f ? 1u : 0u) << ((j0+1) & 31);
        if ((j0 & 31) == 30) { d_mask[i*MASKW + (j0 >> 5)] = mword; mword = 0; }
        float r0 = fmaxf(y0, 0.f), r1 = fmaxf(y1, 0.f);
        u64 rr0 = pk(r0, r0), rr1 = pk(r1, r1);
        ulonglong2 vA = sW2p[j0][0], vB = sW2p[j0][1];
        ulonglong2 uA = sW2p[j0+1][0], uB = sW2p[j0+1][1];
        tp[0] = fma2(rr0, vA.x, tp[0]); tp[1] = fma2(rr0, vA.y, tp[1]);
        tp[2] = fma2(rr0, vB.x, tp[2]); tp[3] = fma2(rr0, vB.y, tp[3]);
        tp[0] = fma2(rr1, uA.x, tp[0]); tp[1] = fma2(rr1, uA.y, tp[1]);
        tp[2] = fma2(rr1, uB.x, tp[2]); tp[3] = fma2(rr1, uB.y, tp[3]);
    }
    float t[8];
    upk(tp[0], t[0], t[1]); upk(tp[1], t[2], t[3]);
    upk(tp[2], t[4], t[5]); upk(tp[3], t[6], t[7]);
    float4* po = (float4*)(d_ts + (size_t)i * D);
    po[0] = make_float4(t[0]*ns, t[1]*ns, t[2]*ns, t[3]*ns);
    po[1] = make_float4(t[4]*ns, t[5]*ns, t[6]*ns, t[7]*ns);
}

// ---------------- h = agg2*nd + b2 + q; zero agg2 ----------------------------
__global__ void k_h(const float* __restrict__ q, const float* __restrict__ b2, int n) {
    int i = blockIdx.x * blockDim.x + threadIdx.x;
    if (i >= n) return;
    float nd = d_ndst[i];
#pragma unroll
    for (int d0 = 0; d0 < D; d0++) {
        d_h[i*D + d0] = d_agg2[i*D + d0] * nd + __ldg(&b2[d0]) + q[i*D + d0];
        d_agg2[i*D + d0] = 0.f;                           // restore invariant
    }
}

// ---------------- pairwise force (2 edges/thread) ---------------------------
__global__ void k_force(const int* __restrict__ src, const int* __restrict__ dst,
                        const float* __restrict__ grav, int e) {
    int t = blockIdx.x * blockDim.x + threadIdx.x;
    float gv = -0.5f * __ldg(grav);
    int base = t * 2;
    int cnt = (base + 2 <= e) ? 2 : (base < e ? 1 : 0);
    int ss[2], tt[2];
    if (cnt == 2) {
        int2 s2 = *(const int2*)(src + base);
        int2 t2 = *(const int2*)(dst + base);
        ss[0] = s2.x; ss[1] = s2.y; tt[0] = t2.x; tt[1] = t2.y;
    } else if (cnt == 1) { ss[0] = src[base]; tt[0] = dst[base]; }
#pragma unroll
    for (int k = 0; k < 2; k++) {
        if (k >= cnt) break;
        int s = ss[k], d2 = tt[k];
        const float4* phs = (const float4*)(d_h + (size_t)s * D);
        const float4* phd = (const float4*)(d_h + (size_t)d2 * D);
        const float4* pms = (const float4*)(d_mdiag + (size_t)s * D);
        const float4* pmd = (const float4*)(d_mdiag + (size_t)d2 * D);
        float4 hs0 = __ldg(phs), hs1 = __ldg(phs+1);
        float4 hd0 = __ldg(phd), hd1 = __ldg(phd+1);
        float4 ms0 = __ldg(pms), ms1 = __ldg(pms+1);
        float4 md0 = __ldg(pmd), md1 = __ldg(pmd+1);
        float c = ms0.x*md0.x + ms0.y*md0.y + ms0.z*md0.z + ms0.w*md0.w
                + ms1.x*md1.x + ms1.y*md1.y + ms1.z*md1.z + ms1.w*md1.w;
        float4 f0, f1;
        f0.x = hs0.x-hd0.x; f0.y = hs0.y-hd0.y; f0.z = hs0.z-hd0.z; f0.w = hs0.w-hd0.w;
        f1.x = hs1.x-hd1.x; f1.y = hs1.y-hd1.y; f1.z = hs1.z-hd1.z; f1.w = hs1.w-hd1.w;
        float r2 = f0.x*f0.x + f0.y*f0.y + f0.z*f0.z + f0.w*f0.w
                 + f1.x*f1.x + f1.y*f1.y + f1.z*f1.z + f1.w*f1.w;
        float inv = rsqrtf(r2);
        float coef = gv * c * inv * inv * inv;
        float4 a0, a1, n0, n1;
        a0.x = coef*f0.x; a0.y = coef*f0.y; a0.z = coef*f0.z; a0.w = coef*f0.w;
        a1.x = coef*f1.x; a1.y = coef*f1.y; a1.z = coef*f1.z; a1.w = coef*f1.w;
        n0.x = -a0.x; n0.y = -a0.y; n0.z = -a0.z; n0.w = -a0.w;
        n1.x = -a1.x; n1.y = -a1.y; n1.z = -a1.z; n1.w = -a1.w;
        float* ps = d_gH + (size_t)s * D;
        float* pt = d_gH + (size_t)d2 * D;
        red_add_v4(ps, a0); red_add_v4(ps + 4, a1);
        red_add_v4(pt, n0); red_add_v4(pt + 4, n1);
    }
}

// ---------------- MLP backward (packed f32x2); zero tmp1 ---------------------
__global__ __launch_bounds__(256) void k_mlp_bwd(const float* __restrict__ W1,
                                                 const float* __restrict__ W2, int n) {
    __shared__ ulonglong2 sW2p[H][2];    // rows of W2, packed in d-pairs
    __shared__ ulonglong2 sW1b[H][2];    // column j of W1, packed in d-pairs
    int tid = threadIdx.x;
    {
        float4 wa = ((const float4*)W2)[tid*2], wb = ((const float4*)W2)[tid*2+1];
        sW2p[tid][0] = make_ulonglong2(pk(wa.x, wa.y), pk(wa.z, wa.w));
        sW2p[tid][1] = make_ulonglong2(pk(wb.x, wb.y), pk(wb.z, wb.w));
        sW1b[tid][0] = make_ulonglong2(pk(W1[0*H+tid], W1[1*H+tid]), pk(W1[2*H+tid], W1[3*H+tid]));
        sW1b[tid][1] = make_ulonglong2(pk(W1[4*H+tid], W1[5*H+tid]), pk(W1[6*H+tid], W1[7*H+tid]));
    }
    __syncthreads();
    int i = blockIdx.x * blockDim.x + tid;
    if (i >= n) return;
    float ns = d_nsrc[i], nd = d_ndst[i];
    float4* pg = (float4*)(d_tmp1 + (size_t)i * D);
    float4 g0 = pg[0], g1 = pg[1];
    pg[0] = make_float4(0.f,0.f,0.f,0.f);               // restore invariant
    pg[1] = make_float4(0.f,0.f,0.f,0.f);
    u64 gp[4] = { pk(g0.x*ns, g0.y*ns), pk(g0.z*ns, g0.w*ns),
                  pk(g1.x*ns, g1.y*ns), pk(g1.z*ns, g1.w*ns) };
    u64 zero2 = pk(0.f, 0.f);
    u64 zc[4] = {zero2, zero2, zero2, zero2};
    unsigned mword = 0;
#pragma unroll 8
    for (int j = 0; j < H; j++) {
        if ((j & 31) == 0) mword = d_mask[i*MASKW + (j >> 5)];
        ulonglong2 vA = sW2p[j][0], vB = sW2p[j][1];
        u64 acc = fma2(gp[0], vA.x, zero2);
        acc = fma2(gp[1], vA.y, acc);
        acc = fma2(gp[2], vB.x, acc);
        acc = fma2(gp[3], vB.y, acc);
        float a0, a1; upk(acc, a0, a1);
        float gh = (a0 + a1) * (float)((mword >> (j & 31)) & 1u);
        u64 gg = pk(gh, gh);
        ulonglong2 wA = sW1b[j][0], wB = sW1b[j][1];
        zc[0] = fma2(gg, wA.x, zc[0]); zc[1] = fma2(gg, wA.y, zc[1]);
        zc[2] = fma2(gg, wB.x, zc[2]); zc[3] = fma2(gg, wB.y, zc[3]);
    }
    float z[8];
    upk(zc[0], z[0], z[1]); upk(zc[1], z[2], z[3]);
    upk(zc[2], z[4], z[5]); upk(zc[3], z[6], z[7]);
    float4* po = (float4*)(d_gz1d + (size_t)i * D);
    po[0] = make_float4(z[0]*nd, z[1]*nd, z[2]*nd, z[3]*nd);
    po[1] = make_float4(z[4]*nd, z[5]*nd, z[6]*nd, z[7]*nd);
}

// ---------------- final: out_q = gH + ns*tmp2; zero gH,tmp2 ------------------
__global__ void k_final(float* __restrict__ out, int n) {
    int i = blockIdx.x * blockDim.x + threadIdx.x;
    if (i >= n) return;
    float ns = d_nsrc[i];
#pragma unroll
    for (int d0 = 0; d0 < D; d0++) {
        out[(size_t)i*16 + d0] = d_gH[i*D + d0] + ns * d_tmp2[i*D + d0];
        d_gH[i*D + d0] = 0.f;                             // restore invariant
        d_tmp2[i*D + d0] = 0.f;
    }
}

// ---------------- launch -----------------------------------------------------
extern "C" void kernel_launch(void* const* d_in, const int* in_sizes, int n_in,
                              void* d_out, int out_size) {
    const float* q    = (const float*)d_in[0];
    const float* p    = (const float*)d_in[1];
    const float* M    = (const float*)d_in[2];
    const int*   src  = (const int*)  d_in[3];
    const int*   dst  = (const int*)  d_in[4];
    const float* W1   = (const float*)d_in[5];
    const float* b1   = (const float*)d_in[6];
    const float* W2   = (const float*)d_in[7];
    const float* b2   = (const float*)d_in[8];
    const float* grav = (const float*)d_in[9];
    float* out = (float*)d_out;

    int n = in_sizes[0] / D;
    int e = in_sizes[3];
    int nb_n  = (n + 255) / 256;
    int nb_e4 = ((e + 3) / 4 + 255) / 256;
    int nb_e2 = ((e + 1) / 2 + 255) / 256;

    k_deg    <<<nb_e4, 256>>>(src, dst, e);
    k_prep   <<<nb_n,  256>>>(q, p, M, out, n);
    k_agg1   <<<nb_e4, 256>>>(src, dst, e);
    k_mlp_fwd<<<nb_n,  256>>>(W1, b1, W2, n);
    k_agg2   <<<nb_e4, 256>>>(src, dst, e);
    k_h      <<<nb_n,  256>>>(q, b2, n);
    k_force  <<<nb_e2, 256>>>(src, dst, grav, e);
    k_aggr1  <<<nb_e4, 256>>>(src, dst, e);
    k_mlp_bwd<<<nb_n,  256>>>(W1, W2, n);
    k_aggr2  <<<nb_e4, 256>>>(src, dst, e);
    k_final  <<<nb_n,  256>>>(out, n);
}

// round 6
// speedup vs baseline: 1.6217x; 1.6217x over previous
#include <cuda_runtime.h>

#define D 8
#define H 256
#define MAXN 100352
#define MASKW (H/32)

// ---------------- scratch (device globals; zero-initialized at module load).
// Invariant: accumulator arrays are zero on entry to kernel_launch and are
// re-zeroed by the kernel that consumes them (graph-replay safe).
__device__ float d_mdiag[MAXN*D];
__device__ float d_qs[MAXN*D];     // q * norm_src
__device__ float d_nsrc[MAXN];
__device__ float d_ndst[MAXN];
__device__ int   d_degout[MAXN];   // accumulator (zeroed by k_prep)
__device__ int   d_degin[MAXN];    // accumulator (zeroed by k_prep)
__device__ float d_agg1[MAXN*D];   // accumulator (zeroed by k_mlp_fwd)
__device__ float d_ts[MAXN*D];
__device__ float d_agg2[MAXN*D];   // accumulator (zeroed by k_h)
__device__ float d_h[MAXN*D];
__device__ float d_gH[MAXN*D];     // accumulator (zeroed by k_final)
__device__ float d_gz1d[MAXN*D];
__device__ float d_tmp1[MAXN*D];   // accumulator (zeroed by k_mlp_bwd)
__device__ float d_tmp2[MAXN*D];   // accumulator (zeroed by k_final)
__device__ unsigned d_mask[MAXN*MASKW];

// ---------------- helpers ---------------------------------------------------
__device__ __forceinline__ void red_add_v4(float* p, float4 v) {
    asm volatile("red.global.add.v4.f32 [%0], {%1,%2,%3,%4};"
                 :: "l"(p), "f"(v.x), "f"(v.y), "f"(v.z), "f"(v.w) : "memory");
}

// ---------------- kernels ---------------------------------------------------
__global__ void k_deg(const int* __restrict__ src, const int* __restrict__ dst, int e) {
    int i = blockIdx.x * blockDim.x + threadIdx.x;
    if (i >= e) return;
    atomicAdd(&d_degout[src[i]], 1);
    atomicAdd(&d_degin[dst[i]], 1);
}

// norms, mass diag extraction, qs pre-scale, dHdP output; zero deg counters
__global__ void k_prep(const float* __restrict__ q, const float* __restrict__ p,
                       const float* __restrict__ M, float* __restrict__ out, int n) {
    int i = blockIdx.x * blockDim.x + threadIdx.x;
    if (i >= n) return;
    int dout = d_degout[i], din = d_degin[i];
    d_degout[i] = 0; d_degin[i] = 0;                      // restore invariant
    float ns = (dout > 0) ? rsqrtf((float)dout) : 1.0f;
    float nd = (din  > 0) ? rsqrtf((float)din)  : 1.0f;
    d_nsrc[i] = ns; d_ndst[i] = nd;
#pragma unroll
    for (int d0 = 0; d0 < D; d0++) {
        float m = M[(size_t)i * (D*D) + d0 * (D+1)];   // diagonal entry
        d_mdiag[i*D + d0] = m;
        float qv = q[i*D + d0];
        d_qs[i*D + d0] = qv * ns;
        out[(size_t)i*16 + 8 + d0] = p[i*D + d0] / m;  // dHdP = M^{-1} p
    }
}

// generic 8-float edge gather/scatter (red.v4 atomics), 1 edge/thread
__device__ __forceinline__ void edge_agg(const int* __restrict__ gi, const int* __restrict__ si,
                                         const float* __restrict__ xin, float* xout, int e) {
    int i = blockIdx.x * blockDim.x + threadIdx.x;
    if (i >= e) return;
    int g = gi[i], s = si[i];
    const float4* ps = (const float4*)(xin + (size_t)g * D);
    float4 a = __ldg(ps), b = __ldg(ps + 1);
    float* po = xout + (size_t)s * D;
    red_add_v4(po, a);
    red_add_v4(po + 4, b);
}

__global__ void k_agg1(const int* __restrict__ src, const int* __restrict__ dst, int e)
{ edge_agg(src, dst, d_qs,  d_agg1, e); }
__global__ void k_agg2(const int* __restrict__ src, const int* __restrict__ dst, int e)
{ edge_agg(src, dst, d_ts,  d_agg2, e); }
__global__ void k_aggr2(const int* __restrict__ src, const int* __restrict__ dst, int e)
{ edge_agg(dst, src, d_gz1d, d_tmp2, e); }

// aggr1 folds the ndst scale into the gather: tmp1[src] += gH[dst] * ndst[dst]
__global__ void k_aggr1(const int* __restrict__ src, const int* __restrict__ dst, int e) {
    int i = blockIdx.x * blockDim.x + threadIdx.x;
    if (i >= e) return;
    int g = dst[i], s = src[i];
    float s0 = __ldg(&d_ndst[g]);
    const float4* ps = (const float4*)(d_gH + (size_t)g * D);
    float4 a = __ldg(ps), b = __ldg(ps + 1);
    a.x *= s0; a.y *= s0; a.z *= s0; a.w *= s0;
    b.x *= s0; b.y *= s0; b.z *= s0; b.w *= s0;
    float* po = d_tmp1 + (size_t)s * D;
    red_add_v4(po, a); red_add_v4(po + 4, b);
}

// node MLP forward: z1 = agg1*nd; y1 = z1 W1 + b1; mask; t = relu(y1) W2; ts = t*ns
// (scalar-float form — R1-proven; also zeroes agg1)
__global__ void k_mlp_fwd(const float* __restrict__ W1, const float* __restrict__ b1,
                          const float* __restrict__ W2, int n) {
    __shared__ float4 sW1[H][2];   // W1 transposed: sW1[j] = W1[:, j]
    __shared__ float4 sW2[H][2];   // W2[j, :]
    __shared__ float  sb1[H];
    int tid = threadIdx.x;
    {
        int j = tid;
        float4 wa, wb;
        wa.x = W1[0*H + j]; wa.y = W1[1*H + j]; wa.z = W1[2*H + j]; wa.w = W1[3*H + j];
        wb.x = W1[4*H + j]; wb.y = W1[5*H + j]; wb.z = W1[6*H + j]; wb.w = W1[7*H + j];
        sW1[j][0] = wa; sW1[j][1] = wb;
        sW2[j][0] = ((const float4*)W2)[j*2];
        sW2[j][1] = ((const float4*)W2)[j*2 + 1];
        sb1[j] = b1[j];
    }
    __syncthreads();
    int i = blockIdx.x * blockDim.x + tid;
    if (i >= n) return;
    float nd = d_ndst[i], ns = d_nsrc[i];
    float4* pz = (float4*)(d_agg1 + (size_t)i * D);
    float4 z0 = pz[0], z1 = pz[1];
    pz[0] = make_float4(0.f,0.f,0.f,0.f);               // restore invariant
    pz[1] = make_float4(0.f,0.f,0.f,0.f);
    z0.x *= nd; z0.y *= nd; z0.z *= nd; z0.w *= nd;
    z1.x *= nd; z1.y *= nd; z1.z *= nd; z1.w *= nd;
    float4 t0 = make_float4(0.f,0.f,0.f,0.f), t1 = make_float4(0.f,0.f,0.f,0.f);
    unsigned mword = 0;
#pragma unroll 8
    for (int j = 0; j < H; j++) {
        float4 wa = sW1[j][0], wb = sW1[j][1];
        float y = sb1[j];
        y += z0.x*wa.x + z0.y*wa.y + z0.z*wa.z + z0.w*wa.w;
        y += z1.x*wb.x + z1.y*wb.y + z1.z*wb.z + z1.w*wb.w;
        unsigned on = (y > 0.f) ? 1u : 0u;
        mword |= on << (j & 31);
        if ((j & 31) == 31) { d_mask[i*MASKW + (j >> 5)] = mword; mword = 0; }
        float r = on ? y : 0.f;
        float4 va = sW2[j][0], vb = sW2[j][1];
        t0.x += r*va.x; t0.y += r*va.y; t0.z += r*va.z; t0.w += r*va.w;
        t1.x += r*vb.x; t1.y += r*vb.y; t1.z += r*vb.z; t1.w += r*vb.w;
    }
    t0.x *= ns; t0.y *= ns; t0.z *= ns; t0.w *= ns;
    t1.x *= ns; t1.y *= ns; t1.z *= ns; t1.w *= ns;
    float4* po = (float4*)(d_ts + (size_t)i * D);
    po[0] = t0; po[1] = t1;
}

// h = agg2*nd + b2 + q; zero agg2
__global__ void k_h(const float* __restrict__ q, const float* __restrict__ b2, int n) {
    int i = blockIdx.x * blockDim.x + threadIdx.x;
    if (i >= n) return;
    float nd = d_ndst[i];
#pragma unroll
    for (int d0 = 0; d0 < D; d0++) {
        d_h[i*D + d0] = d_agg2[i*D + d0] * nd + __ldg(&b2[d0]) + q[i*D + d0];
        d_agg2[i*D + d0] = 0.f;                           // restore invariant
    }
}

// pairwise force: gH[src] += a, gH[dst] -= a ; a = -0.5*g*c*(hs-hd)/r^3
__global__ void k_force(const int* __restrict__ src, const int* __restrict__ dst,
                        const float* __restrict__ grav, int e) {
    int i = blockIdx.x * blockDim.x + threadIdx.x;
    if (i >= e) return;
    int s = src[i], t = dst[i];
    const float4* phs = (const float4*)(d_h + (size_t)s * D);
    const float4* phd = (const float4*)(d_h + (size_t)t * D);
    const float4* pms = (const float4*)(d_mdiag + (size_t)s * D);
    const float4* pmd = (const float4*)(d_mdiag + (size_t)t * D);
    float4 hs0 = __ldg(phs), hs1 = __ldg(phs+1);
    float4 hd0 = __ldg(phd), hd1 = __ldg(phd+1);
    float4 ms0 = __ldg(pms), ms1 = __ldg(pms+1);
    float4 md0 = __ldg(pmd), md1 = __ldg(pmd+1);
    float c = ms0.x*md0.x + ms0.y*md0.y + ms0.z*md0.z + ms0.w*md0.w
            + ms1.x*md1.x + ms1.y*md1.y + ms1.z*md1.z + ms1.w*md1.w;
    float4 f0, f1;
    f0.x = hs0.x - hd0.x; f0.y = hs0.y - hd0.y; f0.z = hs0.z - hd0.z; f0.w = hs0.w - hd0.w;
    f1.x = hs1.x - hd1.x; f1.y = hs1.y - hd1.y; f1.z = hs1.z - hd1.z; f1.w = hs1.w - hd1.w;
    float r2 = f0.x*f0.x + f0.y*f0.y + f0.z*f0.z + f0.w*f0.w
             + f1.x*f1.x + f1.y*f1.y + f1.z*f1.z + f1.w*f1.w;
    float inv = rsqrtf(r2);
    float coef = -0.5f * __ldg(grav) * c * inv * inv * inv;
    float4 a0, a1, n0, n1;
    a0.x = coef*f0.x; a0.y = coef*f0.y; a0.z = coef*f0.z; a0.w = coef*f0.w;
    a1.x = coef*f1.x; a1.y = coef*f1.y; a1.z = coef*f1.z; a1.w = coef*f1.w;
    n0.x = -a0.x; n0.y = -a0.y; n0.z = -a0.z; n0.w = -a0.w;
    n1.x = -a1.x; n1.y = -a1.y; n1.z = -a1.z; n1.w = -a1.w;
    float* ps = d_gH + (size_t)s * D;
    float* pt = d_gH + (size_t)t * D;
    red_add_v4(ps, a0); red_add_v4(ps + 4, a1);
    red_add_v4(pt, n0); red_add_v4(pt + 4, n1);
}

// node MLP backward: gt = tmp1*ns; gh1 = gt W2^T; *mask; gz1 = gh1 W1^T; gz1d = gz1*nd
// (scalar-float form; also zeroes tmp1)
__global__ void k_mlp_bwd(const float* __restrict__ W1, const float* __restrict__ W2, int n) {
    __shared__ float4 sW1[H][2];
    __shared__ float4 sW2[H][2];
    int tid = threadIdx.x;
    {
        int j = tid;
        float4 wa, wb;
        wa.x = W1[0*H + j]; wa.y = W1[1*H + j]; wa.z = W1[2*H + j]; wa.w = W1[3*H + j];
        wb.x = W1[4*H + j]; wb.y = W1[5*H + j]; wb.z = W1[6*H + j]; wb.w = W1[7*H + j];
        sW1[j][0] = wa; sW1[j][1] = wb;
        sW2[j][0] = ((const float4*)W2)[j*2];
        sW2[j][1] = ((const float4*)W2)[j*2 + 1];
    }
    __syncthreads();
    int i = blockIdx.x * blockDim.x + tid;
    if (i >= n) return;
    float ns = d_nsrc[i], nd = d_ndst[i];
    float4* pg = (float4*)(d_tmp1 + (size_t)i * D);
    float4 g0 = pg[0], g1 = pg[1];
    pg[0] = make_float4(0.f,0.f,0.f,0.f);               // restore invariant
    pg[1] = make_float4(0.f,0.f,0.f,0.f);
    g0.x *= ns; g0.y *= ns; g0.z *= ns; g0.w *= ns;
    g1.x *= ns; g1.y *= ns; g1.z *= ns; g1.w *= ns;
    float4 z0 = make_float4(0.f,0.f,0.f,0.f), z1 = make_float4(0.f,0.f,0.f,0.f);
    unsigned mword = 0;
#pragma unroll 8
    for (int j = 0; j < H; j++) {
        if ((j & 31) == 0) mword = d_mask[i*MASKW + (j >> 5)];
        float4 va = sW2[j][0], vb = sW2[j][1];
        float gh = g0.x*va.x + g0.y*va.y + g0.z*va.z + g0.w*va.w
                 + g1.x*vb.x + g1.y*vb.y + g1.z*vb.z + g1.w*vb.w;
        gh *= (float)((mword >> (j & 31)) & 1u);   // relu'(y1)
        float4 wa = sW1[j][0], wb = sW1[j][1];
        z0.x += gh*wa.x; z0.y += gh*wa.y; z0.z += gh*wa.z; z0.w += gh*wa.w;
        z1.x += gh*wb.x; z1.y += gh*wb.y; z1.z += gh*wb.z; z1.w += gh*wb.w;
    }
    z0.x *= nd; z0.y *= nd; z0.z *= nd; z0.w *= nd;
    z1.x *= nd; z1.y *= nd; z1.z *= nd; z1.w *= nd;
    float4* po = (float4*)(d_gz1d + (size_t)i * D);
    po[0] = z0; po[1] = z1;
}

// out[:, 0:8] = gH + nsrc * tmp2; zero gH, tmp2
__global__ void k_final(float* __restrict__ out, int n) {
    int i = blockIdx.x * blockDim.x + threadIdx.x;
    if (i >= n) return;
    float ns = d_nsrc[i];
#pragma unroll
    for (int d0 = 0; d0 < D; d0++) {
        out[(size_t)i*16 + d0] = d_gH[i*D + d0] + ns * d_tmp2[i*D + d0];
        d_gH[i*D + d0] = 0.f;                             // restore invariant
        d_tmp2[i*D + d0] = 0.f;
    }
}

// ---------------- launch ----------------------------------------------------
extern "C" void kernel_launch(void* const* d_in, const int* in_sizes, int n_in,
                              void* d_out, int out_size) {
    const float* q    = (const float*)d_in[0];
    const float* p    = (const float*)d_in[1];
    const float* M    = (const float*)d_in[2];
    const int*   src  = (const int*)  d_in[3];
    const int*   dst  = (const int*)  d_in[4];
    const float* W1   = (const float*)d_in[5];
    const float* b1   = (const float*)d_in[6];
    const float* W2   = (const float*)d_in[7];
    const float* b2   = (const float*)d_in[8];
    const float* grav = (const float*)d_in[9];
    float* out = (float*)d_out;

    int n = in_sizes[0] / D;
    int e = in_sizes[3];
    int nb_n  = (n + 255) / 256;
    int nb_e  = (e + 255) / 256;

    k_deg    <<<nb_e,  256>>>(src, dst, e);
    k_prep   <<<nb_n,  256>>>(q, p, M, out, n);
    k_agg1   <<<nb_e,  256>>>(src, dst, e);
    k_mlp_fwd<<<nb_n,  256>>>(W1, b1, W2, n);
    k_agg2   <<<nb_e,  256>>>(src, dst, e);
    k_h      <<<nb_n,  256>>>(q, b2, n);
    k_force  <<<nb_e,  256>>>(src, dst, grav, e);
    k_aggr1  <<<nb_e,  256>>>(src, dst, e);
    k_mlp_bwd<<<nb_n,  256>>>(W1, W2, n);
    k_aggr2  <<<nb_e,  256>>>(src, dst, e);
    k_final  <<<nb_n,  256>>>(out, n);
}